// round 1
// baseline (speedup 1.0000x reference)
#include <cuda_runtime.h>
#include <cuda_fp16.h>

#define IN_DIM   32768
#define OUT_DIM  32768
#define BATCH    2048
#define RPB      3            // batch rows per block (fp16 rows in smem)
#define NTHREADS 1024
#define SMEM_BYTES (IN_DIM * 4 + IN_DIM * 2)   // half2 plane (rows 0,1) + half plane (row 2)

// Scratch (allocation-free rule: __device__ globals)
__device__ float4 g_coeffs[OUT_DIM];
__device__ int2   g_idx[OUT_DIM];
__device__ int    g_is64;

__constant__ float GC[16][4] = {
    {0.f,0.f,0.f,0.f}, {0.f,0.f,0.f,1.f}, {0.f,1.f,0.f,-1.f}, {0.f,1.f,0.f,0.f},
    {0.f,0.f,1.f,-1.f}, {0.f,0.f,1.f,0.f}, {0.f,1.f,1.f,-2.f}, {0.f,1.f,1.f,-1.f},
    {1.f,-1.f,-1.f,1.f}, {1.f,-1.f,-1.f,2.f}, {1.f,0.f,-1.f,0.f}, {1.f,0.f,-1.f,1.f},
    {1.f,-1.f,0.f,0.f}, {1.f,-1.f,0.f,1.f}, {1.f,0.f,0.f,-1.f}, {1.f,0.f,0.f,0.f}
};

// Detect idx dtype: view first OUT_DIM 32-bit words of idx_a (always in-bounds
// for both int32 [128KB] and int64 [256KB] layouts). For little-endian int64
// with values < 32768, every odd word is 0. For int32 random values, some odd
// word is nonzero with overwhelming probability.
__global__ void detect_kernel(const unsigned* __restrict__ w) {
    __shared__ int s;
    if (threadIdx.x == 0) s = 0;
    __syncthreads();
    unsigned acc = 0;
    for (int i = 2 * threadIdx.x + 1; i < OUT_DIM; i += 2 * blockDim.x) acc |= w[i];
    if (acc) atomicOr(&s, 1);
    __syncthreads();
    if (threadIdx.x == 0) g_is64 = (s == 0) ? 1 : 0;
}

__global__ void prep_kernel(const float* __restrict__ w,
                            const void* __restrict__ pa,
                            const void* __restrict__ pb) {
    int j = blockIdx.x * blockDim.x + threadIdx.x;
    if (j >= OUT_DIM) return;

    float wv[16];
    const float4* w4 = reinterpret_cast<const float4*>(w) + (size_t)j * 4;
#pragma unroll
    for (int q = 0; q < 4; q++) {
        float4 v = w4[q];
        wv[4*q+0] = v.x; wv[4*q+1] = v.y; wv[4*q+2] = v.z; wv[4*q+3] = v.w;
    }
    float m = wv[0];
#pragma unroll
    for (int i = 1; i < 16; i++) m = fmaxf(m, wv[i]);
    float s = 0.f;
#pragma unroll
    for (int i = 0; i < 16; i++) { wv[i] = __expf(wv[i] - m); s += wv[i]; }
    float inv = 1.f / s;

    float c0 = 0.f, ca = 0.f, cb = 0.f, cab = 0.f;
#pragma unroll
    for (int i = 0; i < 16; i++) {
        float p = wv[i];
        c0  = fmaf(p, GC[i][0], c0);
        ca  = fmaf(p, GC[i][1], ca);
        cb  = fmaf(p, GC[i][2], cb);
        cab = fmaf(p, GC[i][3], cab);
    }
    g_coeffs[j] = make_float4(c0 * inv, ca * inv, cb * inv, cab * inv);

    int ia, ib;
    if (g_is64) {
        ia = (int)reinterpret_cast<const long long*>(pa)[j];
        ib = (int)reinterpret_cast<const long long*>(pb)[j];
    } else {
        ia = reinterpret_cast<const int*>(pa)[j];
        ib = reinterpret_cast<const int*>(pb)[j];
    }
    g_idx[j] = make_int2(ia, ib);
}

extern __shared__ unsigned char smem_raw[];

__global__ void __launch_bounds__(NTHREADS, 1)
logic_main(const float* __restrict__ x, float* __restrict__ out) {
    half2* __restrict__ s01 = reinterpret_cast<half2*>(smem_raw);                       // rows 0,1 interleaved
    __half* __restrict__ s2 = reinterpret_cast<__half*>(smem_raw + IN_DIM * sizeof(half2)); // row 2

    int r0 = blockIdx.x * RPB;
    int nr = BATCH - r0; if (nr > RPB) nr = RPB;

    const float4* x0 = reinterpret_cast<const float4*>(x + (size_t)r0 * IN_DIM);
    const float4* x1 = reinterpret_cast<const float4*>(x + (size_t)(r0 + (nr > 1 ? 1 : 0)) * IN_DIM);
    const float4* x2 = reinterpret_cast<const float4*>(x + (size_t)(r0 + (nr > 2 ? 2 : 0)) * IN_DIM);

    // Load + convert: fp32 rows -> fp16 smem planes (coalesced float4 LDG)
    half2* s2h2 = reinterpret_cast<half2*>(s2);
    for (int i = threadIdx.x; i < IN_DIM / 4; i += NTHREADS) {
        float4 v0 = x0[i];
        float4 v1 = x1[i];
        float4 v2 = x2[i];
        s01[4*i+0] = __floats2half2_rn(v0.x, v1.x);
        s01[4*i+1] = __floats2half2_rn(v0.y, v1.y);
        s01[4*i+2] = __floats2half2_rn(v0.z, v1.z);
        s01[4*i+3] = __floats2half2_rn(v0.w, v1.w);
        s2h2[2*i+0] = __floats2half2_rn(v2.x, v2.y);
        s2h2[2*i+1] = __floats2half2_rn(v2.z, v2.w);
    }
    __syncthreads();

    float* o0 = out + (size_t)r0 * OUT_DIM;
    const int full = (nr == RPB);

#pragma unroll 4
    for (int j = threadIdx.x; j < OUT_DIM; j += NTHREADS) {
        int2   ix = __ldg(&g_idx[j]);
        float4 c  = __ldg(&g_coeffs[j]);

        half2 a01 = s01[ix.x];
        half2 b01 = s01[ix.y];
        float a2 = __half2float(s2[ix.x]);
        float b2 = __half2float(s2[ix.y]);

        float a0 = __low2float(a01), a1 = __high2float(a01);
        float b0 = __low2float(b01), b1 = __high2float(b01);

        float r_0 = fmaf(c.w * a0, b0, fmaf(c.y, a0, fmaf(c.z, b0, c.x)));
        float r_1 = fmaf(c.w * a1, b1, fmaf(c.y, a1, fmaf(c.z, b1, c.x)));
        float r_2 = fmaf(c.w * a2, b2, fmaf(c.y, a2, fmaf(c.z, b2, c.x)));

        o0[j] = r_0;
        if (full) {
            o0[OUT_DIM + j] = r_1;
            o0[2 * OUT_DIM + j] = r_2;
        } else {
            if (nr > 1) o0[OUT_DIM + j] = r_1;
            if (nr > 2) o0[2 * OUT_DIM + j] = r_2;
        }
    }
}

extern "C" void kernel_launch(void* const* d_in, const int* in_sizes, int n_in,
                              void* d_out, int out_size) {
    const float* x  = (const float*)d_in[0];
    const void*  ia = d_in[1];
    const void*  ib = d_in[2];
    const float* w  = (const float*)d_in[3];
    float* out = (float*)d_out;

    detect_kernel<<<1, 256>>>((const unsigned*)ia);
    prep_kernel<<<OUT_DIM / 256, 256>>>(w, ia, ib);

    cudaFuncSetAttribute(logic_main, cudaFuncAttributeMaxDynamicSharedMemorySize, SMEM_BYTES);
    int grid = (BATCH + RPB - 1) / RPB;   // 683 blocks
    logic_main<<<grid, NTHREADS, SMEM_BYTES>>>(x, out);
}

// round 3
// speedup vs baseline: 1.1342x; 1.1342x over previous
#include <cuda_runtime.h>
#include <cuda_fp16.h>

#define IN_DIM   32768
#define OUT_DIM  32768
#define BATCH    2048
#define RPB      3            // batch rows per block (fp16 rows in smem)
#define NTHREADS 1024
#define SMEM_BYTES (IN_DIM * 4 + IN_DIM * 2)   // half2 plane (rows 0,1) + half plane (row 2)

// Scratch (allocation-free rule: __device__ globals)
// Packed metadata: 12 B / column  (idx pair in 32 bits, 4 coeffs as fp16)
__device__ unsigned g_pidx[OUT_DIM];
__device__ uint2    g_pc[OUT_DIM];
__device__ int      g_is64;

__constant__ float GC[16][4] = {
    {0.f,0.f,0.f,0.f}, {0.f,0.f,0.f,1.f}, {0.f,1.f,0.f,-1.f}, {0.f,1.f,0.f,0.f},
    {0.f,0.f,1.f,-1.f}, {0.f,0.f,1.f,0.f}, {0.f,1.f,1.f,-2.f}, {0.f,1.f,1.f,-1.f},
    {1.f,-1.f,-1.f,1.f}, {1.f,-1.f,-1.f,2.f}, {1.f,0.f,-1.f,0.f}, {1.f,0.f,-1.f,1.f},
    {1.f,-1.f,0.f,0.f}, {1.f,-1.f,0.f,1.f}, {1.f,0.f,0.f,-1.f}, {1.f,0.f,0.f,0.f}
};

// Detect idx dtype (int64 vs silently-downcast int32): for little-endian int64
// with values < 32768 every odd 32-bit word is 0; for random int32 some odd
// word is nonzero with overwhelming probability.
__global__ void detect_kernel(const unsigned* __restrict__ w) {
    __shared__ int s;
    if (threadIdx.x == 0) s = 0;
    __syncthreads();
    unsigned acc = 0;
    for (int i = 2 * threadIdx.x + 1; i < OUT_DIM; i += 2 * blockDim.x) acc |= w[i];
    if (acc) atomicOr(&s, 1);
    __syncthreads();
    if (threadIdx.x == 0) g_is64 = (s == 0) ? 1 : 0;
}

__global__ void prep_kernel(const float* __restrict__ w,
                            const void* __restrict__ pa,
                            const void* __restrict__ pb) {
    int j = blockIdx.x * blockDim.x + threadIdx.x;
    if (j >= OUT_DIM) return;

    float wv[16];
    const float4* w4 = reinterpret_cast<const float4*>(w) + (size_t)j * 4;
#pragma unroll
    for (int q = 0; q < 4; q++) {
        float4 v = w4[q];
        wv[4*q+0] = v.x; wv[4*q+1] = v.y; wv[4*q+2] = v.z; wv[4*q+3] = v.w;
    }
    float m = wv[0];
#pragma unroll
    for (int i = 1; i < 16; i++) m = fmaxf(m, wv[i]);
    float s = 0.f;
#pragma unroll
    for (int i = 0; i < 16; i++) { wv[i] = __expf(wv[i] - m); s += wv[i]; }
    float inv = 1.f / s;

    float c0 = 0.f, ca = 0.f, cb = 0.f, cab = 0.f;
#pragma unroll
    for (int i = 0; i < 16; i++) {
        float p = wv[i];
        c0  = fmaf(p, GC[i][0], c0);
        ca  = fmaf(p, GC[i][1], ca);
        cb  = fmaf(p, GC[i][2], cb);
        cab = fmaf(p, GC[i][3], cab);
    }
    c0 *= inv; ca *= inv; cb *= inv; cab *= inv;

    __half2 h01 = __floats2half2_rn(c0, ca);
    __half2 h23 = __floats2half2_rn(cb, cab);
    uint2 pc;
    pc.x = *reinterpret_cast<unsigned*>(&h01);
    pc.y = *reinterpret_cast<unsigned*>(&h23);
    g_pc[j] = pc;

    unsigned ia, ib;
    if (g_is64) {
        ia = (unsigned)reinterpret_cast<const long long*>(pa)[j];
        ib = (unsigned)reinterpret_cast<const long long*>(pb)[j];
    } else {
        ia = (unsigned)reinterpret_cast<const int*>(pa)[j];
        ib = (unsigned)reinterpret_cast<const int*>(pb)[j];
    }
    g_pidx[j] = ia | (ib << 16);
}

extern __shared__ unsigned char smem_raw[];

__global__ void __launch_bounds__(NTHREADS, 1)
logic_main(const float* __restrict__ x, float* __restrict__ out) {
    half2* __restrict__ s01 = reinterpret_cast<half2*>(smem_raw);                            // rows 0,1 interleaved
    __half* __restrict__ s2 = reinterpret_cast<__half*>(smem_raw + IN_DIM * sizeof(half2)); // row 2

    int r0 = blockIdx.x * RPB;
    int nr = BATCH - r0; if (nr > RPB) nr = RPB;

    const float4* x0 = reinterpret_cast<const float4*>(x + (size_t)r0 * IN_DIM);
    const float4* x1 = reinterpret_cast<const float4*>(x + (size_t)(r0 + (nr > 1 ? 1 : 0)) * IN_DIM);
    const float4* x2 = reinterpret_cast<const float4*>(x + (size_t)(r0 + (nr > 2 ? 2 : 0)) * IN_DIM);

    // Load + convert: fp32 rows -> fp16 smem planes (coalesced float4 LDG)
    half2* s2h2 = reinterpret_cast<half2*>(s2);
    for (int i = threadIdx.x; i < IN_DIM / 4; i += NTHREADS) {
        float4 v0 = x0[i];
        float4 v1 = x1[i];
        float4 v2 = x2[i];
        s01[4*i+0] = __floats2half2_rn(v0.x, v1.x);
        s01[4*i+1] = __floats2half2_rn(v0.y, v1.y);
        s01[4*i+2] = __floats2half2_rn(v0.z, v1.z);
        s01[4*i+3] = __floats2half2_rn(v0.w, v1.w);
        s2h2[2*i+0] = __floats2half2_rn(v2.x, v2.y);
        s2h2[2*i+1] = __floats2half2_rn(v2.z, v2.w);
    }
    __syncthreads();

    float2* o0 = reinterpret_cast<float2*>(out + (size_t)r0 * OUT_DIM);
    float2* o1 = o0 + OUT_DIM / 2;
    float2* o2 = o1 + OUT_DIM / 2;
    const int full = (nr == RPB);

    const uint2* __restrict__ pidx2 = reinterpret_cast<const uint2*>(g_pidx);
    const uint4* __restrict__ pc4   = reinterpret_cast<const uint4*>(g_pc);

#pragma unroll 4
    for (int t = threadIdx.x; t < OUT_DIM / 2; t += NTHREADS) {
        uint2 ii = __ldg(&pidx2[t]);   // two columns' packed idx
        uint4 cc = __ldg(&pc4[t]);     // two columns' packed coeffs

        unsigned iaA = ii.x & 0xFFFFu, ibA = ii.x >> 16;   // column A (even)
        unsigned iaB = ii.y & 0xFFFFu, ibB = ii.y >> 16;   // column B (odd)

        half2 aA01 = s01[iaA], bA01 = s01[ibA];
        half2 aB01 = s01[iaB], bB01 = s01[ibB];
        float aA2 = __half2float(s2[iaA]), bA2 = __half2float(s2[ibA]);
        float aB2 = __half2float(s2[iaB]), bB2 = __half2float(s2[ibB]);

        float2 cA01 = __half22float2(*reinterpret_cast<__half2*>(&cc.x)); // c0, ca
        float2 cA23 = __half22float2(*reinterpret_cast<__half2*>(&cc.y)); // cb, cab
        float2 cB01 = __half22float2(*reinterpret_cast<__half2*>(&cc.z));
        float2 cB23 = __half22float2(*reinterpret_cast<__half2*>(&cc.w));

        float2 aAf = __half22float2(aA01), bAf = __half22float2(bA01);
        float2 aBf = __half22float2(aB01), bBf = __half22float2(bB01);

        // r = fmaf(a, fmaf(cab,b,ca), fmaf(cb,b,c0))   (3 FMA per output)
        float rA0 = fmaf(aAf.x, fmaf(cA23.y, bAf.x, cA01.y), fmaf(cA23.x, bAf.x, cA01.x));
        float rA1 = fmaf(aAf.y, fmaf(cA23.y, bAf.y, cA01.y), fmaf(cA23.x, bAf.y, cA01.x));
        float rA2 = fmaf(aA2,   fmaf(cA23.y, bA2,   cA01.y), fmaf(cA23.x, bA2,   cA01.x));

        float rB0 = fmaf(aBf.x, fmaf(cB23.y, bBf.x, cB01.y), fmaf(cB23.x, bBf.x, cB01.x));
        float rB1 = fmaf(aBf.y, fmaf(cB23.y, bBf.y, cB01.y), fmaf(cB23.x, bBf.y, cB01.x));
        float rB2 = fmaf(aB2,   fmaf(cB23.y, bB2,   cB01.y), fmaf(cB23.x, bB2,   cB01.x));

        o0[t] = make_float2(rA0, rB0);
        if (full) {
            o1[t] = make_float2(rA1, rB1);
            o2[t] = make_float2(rA2, rB2);
        } else {
            if (nr > 1) o1[t] = make_float2(rA1, rB1);
            if (nr > 2) o2[t] = make_float2(rA2, rB2);
        }
    }
}

extern "C" void kernel_launch(void* const* d_in, const int* in_sizes, int n_in,
                              void* d_out, int out_size) {
    const float* x  = (const float*)d_in[0];
    const void*  ia = d_in[1];
    const void*  ib = d_in[2];
    const float* w  = (const float*)d_in[3];
    float* out = (float*)d_out;

    detect_kernel<<<1, 256>>>((const unsigned*)ia);
    prep_kernel<<<OUT_DIM / 256, 256>>>(w, ia, ib);

    cudaFuncSetAttribute(logic_main, cudaFuncAttributeMaxDynamicSharedMemorySize, SMEM_BYTES);
    int grid = (BATCH + RPB - 1) / RPB;   // 683 blocks
    logic_main<<<grid, NTHREADS, SMEM_BYTES>>>(x, out);
}

// round 4
// speedup vs baseline: 1.1876x; 1.0471x over previous
#include <cuda_runtime.h>
#include <cuda_fp16.h>

#define IN_DIM   32768
#define OUT_DIM  32768
#define BATCH    2048
#define RPB      3            // batch rows per block (fp16 rows in smem)
#define NTHREADS 512
#define SMEM_BYTES (IN_DIM * 4 + IN_DIM * 2)   // half2 plane (rows 0,1) + half plane (row 2)

// Scratch (allocation-free rule: __device__ globals)
// Packed metadata: 12 B / column  (idx pair in 32 bits, 4 coeffs as fp16)
__device__ unsigned g_pidx[OUT_DIM];
__device__ uint2    g_pc[OUT_DIM];

__constant__ float GC[16][4] = {
    {0.f,0.f,0.f,0.f}, {0.f,0.f,0.f,1.f}, {0.f,1.f,0.f,-1.f}, {0.f,1.f,0.f,0.f},
    {0.f,0.f,1.f,-1.f}, {0.f,0.f,1.f,0.f}, {0.f,1.f,1.f,-2.f}, {0.f,1.f,1.f,-1.f},
    {1.f,-1.f,-1.f,1.f}, {1.f,-1.f,-1.f,2.f}, {1.f,0.f,-1.f,0.f}, {1.f,0.f,-1.f,1.f},
    {1.f,-1.f,0.f,0.f}, {1.f,-1.f,0.f,1.f}, {1.f,0.f,0.f,-1.f}, {1.f,0.f,0.f,0.f}
};

// prep: softmax coeffs -> fp16 pack, idx pair -> 16+16 bit pack.
// idx dtype detection is done per-block (no separate kernel): every block scans
// the SAME first 512 32-bit words of idx_a. For little-endian int64 values
// < 32768, every odd word is 0. For int32 random values, 256 odd words being
// all zero has probability ~2^-3840.
__global__ void prep_kernel(const float* __restrict__ w,
                            const void* __restrict__ pa,
                            const void* __restrict__ pb) {
    const unsigned* wa = (const unsigned*)pa;
    int is64 = !__syncthreads_or(wa[2 * threadIdx.x + 1] != 0u);

    int j = blockIdx.x * blockDim.x + threadIdx.x;
    if (j >= OUT_DIM) return;

    float wv[16];
    const float4* w4 = reinterpret_cast<const float4*>(w) + (size_t)j * 4;
#pragma unroll
    for (int q = 0; q < 4; q++) {
        float4 v = w4[q];
        wv[4*q+0] = v.x; wv[4*q+1] = v.y; wv[4*q+2] = v.z; wv[4*q+3] = v.w;
    }
    float m = wv[0];
#pragma unroll
    for (int i = 1; i < 16; i++) m = fmaxf(m, wv[i]);
    float s = 0.f;
#pragma unroll
    for (int i = 0; i < 16; i++) { wv[i] = __expf(wv[i] - m); s += wv[i]; }
    float inv = 1.f / s;

    float c0 = 0.f, ca = 0.f, cb = 0.f, cab = 0.f;
#pragma unroll
    for (int i = 0; i < 16; i++) {
        float p = wv[i];
        c0  = fmaf(p, GC[i][0], c0);
        ca  = fmaf(p, GC[i][1], ca);
        cb  = fmaf(p, GC[i][2], cb);
        cab = fmaf(p, GC[i][3], cab);
    }
    c0 *= inv; ca *= inv; cb *= inv; cab *= inv;

    __half2 h01 = __floats2half2_rn(c0, ca);
    __half2 h23 = __floats2half2_rn(cb, cab);
    uint2 pc;
    pc.x = *reinterpret_cast<unsigned*>(&h01);
    pc.y = *reinterpret_cast<unsigned*>(&h23);
    g_pc[j] = pc;

    unsigned ia, ib;
    if (is64) {
        ia = (unsigned)reinterpret_cast<const long long*>(pa)[j];
        ib = (unsigned)reinterpret_cast<const long long*>(pb)[j];
    } else {
        ia = (unsigned)reinterpret_cast<const int*>(pa)[j];
        ib = (unsigned)reinterpret_cast<const int*>(pb)[j];
    }
    g_pidx[j] = ia | (ib << 16);
}

extern __shared__ unsigned char smem_raw[];

// One column's contribution for one batch row (3 FMA)
__device__ __forceinline__ float gate3(float a, float b, float2 c01, float2 c23) {
    return fmaf(a, fmaf(c23.y, b, c01.y), fmaf(c23.x, b, c01.x));
}

__global__ void __launch_bounds__(NTHREADS, 1)
logic_main(const float* __restrict__ x, float* __restrict__ out) {
    half2* __restrict__ s01 = reinterpret_cast<half2*>(smem_raw);                            // rows 0,1 interleaved
    __half* __restrict__ s2 = reinterpret_cast<__half*>(smem_raw + IN_DIM * sizeof(half2)); // row 2

    int r0 = blockIdx.x * RPB;
    int nr = BATCH - r0; if (nr > RPB) nr = RPB;

    const float4* x0 = reinterpret_cast<const float4*>(x + (size_t)r0 * IN_DIM);
    const float4* x1 = reinterpret_cast<const float4*>(x + (size_t)(r0 + (nr > 1 ? 1 : 0)) * IN_DIM);
    const float4* x2 = reinterpret_cast<const float4*>(x + (size_t)(r0 + (nr > 2 ? 2 : 0)) * IN_DIM);

    // Load + convert: fp32 rows -> fp16 smem planes (streaming loads, read-once)
    half2* s2h2 = reinterpret_cast<half2*>(s2);
#pragma unroll 2
    for (int i = threadIdx.x; i < IN_DIM / 4; i += NTHREADS) {
        float4 v0 = __ldcs(&x0[i]);
        float4 v1 = __ldcs(&x1[i]);
        float4 v2 = __ldcs(&x2[i]);
        s01[4*i+0] = __floats2half2_rn(v0.x, v1.x);
        s01[4*i+1] = __floats2half2_rn(v0.y, v1.y);
        s01[4*i+2] = __floats2half2_rn(v0.z, v1.z);
        s01[4*i+3] = __floats2half2_rn(v0.w, v1.w);
        s2h2[2*i+0] = __floats2half2_rn(v2.x, v2.y);
        s2h2[2*i+1] = __floats2half2_rn(v2.z, v2.w);
    }
    __syncthreads();

    float4* o0 = reinterpret_cast<float4*>(out + (size_t)r0 * OUT_DIM);
    float4* o1 = o0 + OUT_DIM / 4;
    float4* o2 = o1 + OUT_DIM / 4;
    const int full = (nr == RPB);

    const uint4* __restrict__ pidx4 = reinterpret_cast<const uint4*>(g_pidx); // 4 cols / load
    const uint4* __restrict__ pc4   = reinterpret_cast<const uint4*>(g_pc);   // 2 cols / load

#pragma unroll 4
    for (int t = threadIdx.x; t < OUT_DIM / 4; t += NTHREADS) {
        uint4 ii  = __ldg(&pidx4[t]);       // packed idx for cols 4t..4t+3
        uint4 ccA = __ldg(&pc4[2*t]);       // coeffs cols 4t, 4t+1
        uint4 ccB = __ldg(&pc4[2*t+1]);     // coeffs cols 4t+2, 4t+3

        unsigned iw[4] = {ii.x, ii.y, ii.z, ii.w};
        unsigned cw[8] = {ccA.x, ccA.y, ccA.z, ccA.w, ccB.x, ccB.y, ccB.z, ccB.w};

        float4 r_0, r_1, r_2;
        float* p0 = &r_0.x; float* p1 = &r_1.x; float* p2 = &r_2.x;

#pragma unroll
        for (int k = 0; k < 4; k++) {
            unsigned ia = iw[k] & 0xFFFFu, ib = iw[k] >> 16;
            half2 a01 = s01[ia], b01 = s01[ib];
            float a2 = __half2float(s2[ia]);
            float b2 = __half2float(s2[ib]);

            float2 c01 = __half22float2(*reinterpret_cast<__half2*>(&cw[2*k+0])); // c0, ca
            float2 c23 = __half22float2(*reinterpret_cast<__half2*>(&cw[2*k+1])); // cb, cab

            float2 af = __half22float2(a01), bf = __half22float2(b01);
            p0[k] = gate3(af.x, bf.x, c01, c23);
            p1[k] = gate3(af.y, bf.y, c01, c23);
            p2[k] = gate3(a2,   b2,   c01, c23);
        }

        __stcs(&o0[t], r_0);
        if (full) {
            __stcs(&o1[t], r_1);
            __stcs(&o2[t], r_2);
        } else {
            if (nr > 1) __stcs(&o1[t], r_1);
            if (nr > 2) __stcs(&o2[t], r_2);
        }
    }
}

extern "C" void kernel_launch(void* const* d_in, const int* in_sizes, int n_in,
                              void* d_out, int out_size) {
    const float* x  = (const float*)d_in[0];
    const void*  ia = d_in[1];
    const void*  ib = d_in[2];
    const float* w  = (const float*)d_in[3];
    float* out = (float*)d_out;

    prep_kernel<<<OUT_DIM / 256, 256>>>(w, ia, ib);

    cudaFuncSetAttribute(logic_main, cudaFuncAttributeMaxDynamicSharedMemorySize, SMEM_BYTES);
    int grid = (BATCH + RPB - 1) / RPB;   // 683 blocks
    logic_main<<<grid, NTHREADS, SMEM_BYTES>>>(x, out);
}

// round 5
// speedup vs baseline: 1.2463x; 1.0494x over previous
#include <cuda_runtime.h>
#include <cuda_fp16.h>

#define IN_DIM   32768
#define OUT_DIM  32768
#define BATCH    2048
#define RPB      2            // batch rows per block (half2-interleaved in smem)
#define NTHREADS 1024
#define SMEM_BYTES (IN_DIM * 4)   // one half2 plane: rows 0,1 interleaved

// Scratch (allocation-free rule: __device__ globals)
// Packed metadata: 12 B / column  (idx pair in 32 bits, 4 coeffs as fp16)
__device__ unsigned g_pidx[OUT_DIM];
__device__ uint2    g_pc[OUT_DIM];

__constant__ float GC[16][4] = {
    {0.f,0.f,0.f,0.f}, {0.f,0.f,0.f,1.f}, {0.f,1.f,0.f,-1.f}, {0.f,1.f,0.f,0.f},
    {0.f,0.f,1.f,-1.f}, {0.f,0.f,1.f,0.f}, {0.f,1.f,1.f,-2.f}, {0.f,1.f,1.f,-1.f},
    {1.f,-1.f,-1.f,1.f}, {1.f,-1.f,-1.f,2.f}, {1.f,0.f,-1.f,0.f}, {1.f,0.f,-1.f,1.f},
    {1.f,-1.f,0.f,0.f}, {1.f,-1.f,0.f,1.f}, {1.f,0.f,0.f,-1.f}, {1.f,0.f,0.f,0.f}
};

// prep: softmax coeffs -> fp16 pack, idx pair -> 16+16 bit pack.
// idx dtype detection per-block: every block scans the SAME first 512 32-bit
// words of idx_a. little-endian int64 values < 32768 -> all odd words 0;
// random int32 -> some odd word nonzero w.p. 1 - 2^-3840.
__global__ void prep_kernel(const float* __restrict__ w,
                            const void* __restrict__ pa,
                            const void* __restrict__ pb) {
    const unsigned* wa = (const unsigned*)pa;
    int is64 = !__syncthreads_or(wa[2 * threadIdx.x + 1] != 0u);

    int j = blockIdx.x * blockDim.x + threadIdx.x;
    if (j >= OUT_DIM) return;

    float wv[16];
    const float4* w4 = reinterpret_cast<const float4*>(w) + (size_t)j * 4;
#pragma unroll
    for (int q = 0; q < 4; q++) {
        float4 v = w4[q];
        wv[4*q+0] = v.x; wv[4*q+1] = v.y; wv[4*q+2] = v.z; wv[4*q+3] = v.w;
    }
    float m = wv[0];
#pragma unroll
    for (int i = 1; i < 16; i++) m = fmaxf(m, wv[i]);
    float s = 0.f;
#pragma unroll
    for (int i = 0; i < 16; i++) { wv[i] = __expf(wv[i] - m); s += wv[i]; }
    float inv = 1.f / s;

    float c0 = 0.f, ca = 0.f, cb = 0.f, cab = 0.f;
#pragma unroll
    for (int i = 0; i < 16; i++) {
        float p = wv[i];
        c0  = fmaf(p, GC[i][0], c0);
        ca  = fmaf(p, GC[i][1], ca);
        cb  = fmaf(p, GC[i][2], cb);
        cab = fmaf(p, GC[i][3], cab);
    }
    c0 *= inv; ca *= inv; cb *= inv; cab *= inv;

    __half2 h01 = __floats2half2_rn(c0, ca);
    __half2 h23 = __floats2half2_rn(cb, cab);
    uint2 pc;
    pc.x = *reinterpret_cast<unsigned*>(&h01);
    pc.y = *reinterpret_cast<unsigned*>(&h23);
    g_pc[j] = pc;

    unsigned ia, ib;
    if (is64) {
        ia = (unsigned)reinterpret_cast<const long long*>(pa)[j];
        ib = (unsigned)reinterpret_cast<const long long*>(pb)[j];
    } else {
        ia = (unsigned)reinterpret_cast<const int*>(pa)[j];
        ib = (unsigned)reinterpret_cast<const int*>(pb)[j];
    }
    g_pidx[j] = ia | (ib << 16);
}

extern __shared__ unsigned char smem_raw[];

// One column's contribution for one batch row (3 FMA)
__device__ __forceinline__ float gate3(float a, float b, float2 c01, float2 c23) {
    return fmaf(a, fmaf(c23.y, b, c01.y), fmaf(c23.x, b, c01.x));
}

__global__ void __launch_bounds__(NTHREADS, 1)
logic_main(const float* __restrict__ x, float* __restrict__ out) {
    half2* __restrict__ s01 = reinterpret_cast<half2*>(smem_raw);  // rows 0,1 interleaved

    int r0 = blockIdx.x * RPB;   // BATCH % RPB == 0: no tail

    const float4* x0 = reinterpret_cast<const float4*>(x + (size_t)r0 * IN_DIM);
    const float4* x1 = reinterpret_cast<const float4*>(x + (size_t)(r0 + 1) * IN_DIM);

    // Load + convert: fp32 rows -> one fp16 half2 plane (streaming, read-once)
#pragma unroll 2
    for (int i = threadIdx.x; i < IN_DIM / 4; i += NTHREADS) {
        float4 v0 = __ldcs(&x0[i]);
        float4 v1 = __ldcs(&x1[i]);
        s01[4*i+0] = __floats2half2_rn(v0.x, v1.x);
        s01[4*i+1] = __floats2half2_rn(v0.y, v1.y);
        s01[4*i+2] = __floats2half2_rn(v0.z, v1.z);
        s01[4*i+3] = __floats2half2_rn(v0.w, v1.w);
    }
    __syncthreads();

    float4* o0 = reinterpret_cast<float4*>(out + (size_t)r0 * OUT_DIM);
    float4* o1 = o0 + OUT_DIM / 4;

    const uint4* __restrict__ pidx4 = reinterpret_cast<const uint4*>(g_pidx); // 4 cols / load
    const uint4* __restrict__ pc4   = reinterpret_cast<const uint4*>(g_pc);   // 2 cols / load

#pragma unroll 4
    for (int t = threadIdx.x; t < OUT_DIM / 4; t += NTHREADS) {
        uint4 ii  = __ldg(&pidx4[t]);       // packed idx for cols 4t..4t+3
        uint4 ccA = __ldg(&pc4[2*t]);       // coeffs cols 4t, 4t+1
        uint4 ccB = __ldg(&pc4[2*t+1]);     // coeffs cols 4t+2, 4t+3

        unsigned iw[4] = {ii.x, ii.y, ii.z, ii.w};
        unsigned cw[8] = {ccA.x, ccA.y, ccA.z, ccA.w, ccB.x, ccB.y, ccB.z, ccB.w};

        float4 r_0, r_1;
        float* p0 = &r_0.x; float* p1 = &r_1.x;

#pragma unroll
        for (int k = 0; k < 4; k++) {
            unsigned ia = iw[k] & 0xFFFFu, ib = iw[k] >> 16;
            half2 a01 = s01[ia], b01 = s01[ib];

            float2 c01 = __half22float2(*reinterpret_cast<__half2*>(&cw[2*k+0])); // c0, ca
            float2 c23 = __half22float2(*reinterpret_cast<__half2*>(&cw[2*k+1])); // cb, cab

            float2 af = __half22float2(a01), bf = __half22float2(b01);
            p0[k] = gate3(af.x, bf.x, c01, c23);
            p1[k] = gate3(af.y, bf.y, c01, c23);
        }

        __stcs(&o0[t], r_0);
        __stcs(&o1[t], r_1);
    }
}

extern "C" void kernel_launch(void* const* d_in, const int* in_sizes, int n_in,
                              void* d_out, int out_size) {
    const float* x  = (const float*)d_in[0];
    const void*  ia = d_in[1];
    const void*  ib = d_in[2];
    const float* w  = (const float*)d_in[3];
    float* out = (float*)d_out;

    prep_kernel<<<OUT_DIM / 256, 256>>>(w, ia, ib);

    cudaFuncSetAttribute(logic_main, cudaFuncAttributeMaxDynamicSharedMemorySize, SMEM_BYTES);
    int grid = BATCH / RPB;   // 1024 blocks
    logic_main<<<grid, NTHREADS, SMEM_BYTES>>>(x, out);
}